// round 4
// baseline (speedup 1.0000x reference)
#include <cuda_runtime.h>
#include <cuda_bf16.h>
#include <cstdint>

// ---------------- problem dims ----------------
#define B_ 8192
#define V_ 1024
#define E_ 640
#define H_ 640
#define L_ 2
#define D_ 512
#define J_ 640

// ---------------- GEMM smem layout ----------------
#define ROWB   80                    // bytes per smem row: 32 bf16 (64B) + 16B pad
#define TILEB  (128 * ROWB)          // one 128x32 bf16 tile = 10240 B
#define STAGEB (4 * TILEB)           // Ahi, Alo, Whi, Wlo       = 40960 B
#define NSTAGE 4
#define SMEMB  (NSTAGE * STAGEB)     // 163840 B

// ================= low-level helpers (base sm_100 ISA only) =================
__device__ __forceinline__ uint32_t smem_to_u32(const void* p) {
    uint32_t a;
    asm("{ .reg .u64 t; cvta.to.shared.u64 t, %1; cvt.u32.u64 %0, t; }"
        : "=r"(a) : "l"(p));
    return a;
}
__device__ __forceinline__ void cp_async16(uint32_t saddr, const void* gptr) {
    asm volatile("cp.async.cg.shared.global [%0], [%1], 16;"
                 :: "r"(saddr), "l"(gptr));
}
__device__ __forceinline__ void cp_commit() {
    asm volatile("cp.async.commit_group;");
}
template <int N>
__device__ __forceinline__ void cp_wait() {
    asm volatile("cp.async.wait_group %0;" :: "n"(N));
}
__device__ __forceinline__ void ldsm_x4(uint32_t* r, uint32_t addr) {
    asm volatile("ldmatrix.sync.aligned.m8n8.x4.shared.b16 {%0,%1,%2,%3}, [%4];"
                 : "=r"(r[0]), "=r"(r[1]), "=r"(r[2]), "=r"(r[3]) : "r"(addr));
}
__device__ __forceinline__ void mma_bf16(float* c, const uint32_t* a,
                                         uint32_t b0, uint32_t b1) {
    asm volatile(
        "mma.sync.aligned.m16n8k16.row.col.f32.bf16.bf16.f32 "
        "{%0,%1,%2,%3}, {%4,%5,%6,%7}, {%8,%9}, {%0,%1,%2,%3};"
        : "+f"(c[0]), "+f"(c[1]), "+f"(c[2]), "+f"(c[3])
        : "r"(a[0]), "r"(a[1]), "r"(a[2]), "r"(a[3]), "r"(b0), "r"(b1));
}

// ================= scratch (no allocations allowed) =================
__device__ float g_gates[B_ * 4 * H_];
__device__ __align__(16) __nv_bfloat16 g_xhi[B_ * E_],  g_xlo[B_ * E_];
__device__ __align__(16) __nv_bfloat16 g_h0hi[L_ * B_ * H_], g_h0lo[L_ * B_ * H_];
__device__ __align__(16) __nv_bfloat16 g_h1hi[L_ * B_ * H_], g_h1lo[L_ * B_ * H_];
__device__ __align__(16) __nv_bfloat16 g_enchi[B_ * D_], g_enclo[B_ * D_];
__device__ __align__(16) __nv_bfloat16 g_zhi[B_ * J_],  g_zlo[B_ * J_];
__device__ __align__(16) __nv_bfloat16 g_wihhi[L_ * 4 * H_ * H_], g_wihlo[L_ * 4 * H_ * H_];
__device__ __align__(16) __nv_bfloat16 g_whhhi[L_ * 4 * H_ * H_], g_whhlo[L_ * 4 * H_ * H_];
__device__ __align__(16) __nv_bfloat16 g_wenchi[J_ * D_], g_wenclo[J_ * D_];
__device__ __align__(16) __nv_bfloat16 g_wpredhi[J_ * H_], g_wpredlo[J_ * H_];
__device__ __align__(16) __nv_bfloat16 g_wouthi[V_ * J_], g_woutlo[V_ * J_];

// ================= elementwise kernels =================
__device__ __forceinline__ void split1(float v, __nv_bfloat16& h, __nv_bfloat16& l) {
    h = __float2bfloat16_rn(v);
    l = __float2bfloat16_rn(v - __bfloat162float(h));
}

__global__ void split_bf16(const float4* __restrict__ in,
                           __nv_bfloat162* __restrict__ hi,
                           __nv_bfloat162* __restrict__ lo, int n4) {
    int i = blockIdx.x * blockDim.x + threadIdx.x;
    if (i >= n4) return;
    float4 v = in[i];
    __nv_bfloat16 hx, lx, hy, ly, hz, lz, hw, lw;
    split1(v.x, hx, lx); split1(v.y, hy, ly);
    split1(v.z, hz, lz); split1(v.w, hw, lw);
    __nv_bfloat162 t;
    t.x = hx; t.y = hy; hi[2 * i]     = t;
    t.x = hz; t.y = hw; hi[2 * i + 1] = t;
    t.x = lx; t.y = ly; lo[2 * i]     = t;
    t.x = lz; t.y = lw; lo[2 * i + 1] = t;
}

__global__ void gather_split(const int* __restrict__ ids,
                             const float4* __restrict__ emb,
                             __nv_bfloat162* __restrict__ xhi,
                             __nv_bfloat162* __restrict__ xlo) {
    int i = blockIdx.x * blockDim.x + threadIdx.x;   // over B_*(E_/4)
    if (i >= B_ * (E_ / 4)) return;
    int b = i / (E_ / 4);
    int q = i - b * (E_ / 4);
    float4 v = emb[(size_t)ids[b] * (E_ / 4) + q];
    __nv_bfloat16 hx, lx, hy, ly, hz, lz, hw, lw;
    split1(v.x, hx, lx); split1(v.y, hy, ly);
    split1(v.z, hz, lz); split1(v.w, hw, lw);
    size_t o = (size_t)b * (E_ / 2) + q * 2;
    __nv_bfloat162 t;
    t.x = hx; t.y = hy; xhi[o]     = t;
    t.x = hz; t.y = hw; xhi[o + 1] = t;
    t.x = lx; t.y = ly; xlo[o]     = t;
    t.x = lz; t.y = lw; xlo[o + 1] = t;
}

__device__ __forceinline__ float sigmoidf_(float x) {
    return 1.0f / (1.0f + expf(-x));
}

__global__ void lstm_cell(const float* __restrict__ gates,
                          const float* __restrict__ c0,
                          float* __restrict__ h1f, float* __restrict__ c1f,
                          __nv_bfloat16* __restrict__ h1hi,
                          __nv_bfloat16* __restrict__ h1lo) {
    int i = blockIdx.x * blockDim.x + threadIdx.x;   // over B_*H_
    if (i >= B_ * H_) return;
    int b = i / H_;
    int n = i - b * H_;
    const float* g = gates + (size_t)b * (4 * H_);
    float ig = sigmoidf_(g[n]);
    float fg = sigmoidf_(g[H_ + n]);
    float gg = tanhf(g[2 * H_ + n]);
    float og = sigmoidf_(g[3 * H_ + n]);
    float c  = fg * c0[i] + ig * gg;
    float h  = og * tanhf(c);
    c1f[i] = c;
    h1f[i] = h;
    __nv_bfloat16 hh, hl;
    split1(h, hh, hl);
    h1hi[i] = hh;
    h1lo[i] = hl;
}

// ================= split-bf16 HMMA GEMM =================
// C[M,N] = A1*W1^T + A2*W2^T (+b1(+b2), opt relu), 2-way bf16 split:
//   hi*hi + hi*lo + lo*hi per operand pair.
// CTA tile 128x128, 512 threads = 16 warps (4x4), warp tile 32x32.
// K chunks of 32, 4-stage cp.async pipeline.
// If Chi != nullptr: write hi/lo bf16 split of C; else fp32 to Cf.
__global__ void __launch_bounds__(512, 1)
gemm_hmma(const __nv_bfloat16* __restrict__ A1h, const __nv_bfloat16* __restrict__ A1l,
          const __nv_bfloat16* __restrict__ W1h, const __nv_bfloat16* __restrict__ W1l, int K1,
          const __nv_bfloat16* __restrict__ A2h, const __nv_bfloat16* __restrict__ A2l,
          const __nv_bfloat16* __restrict__ W2h, const __nv_bfloat16* __restrict__ W2l, int K2,
          const float* __restrict__ b1, const float* __restrict__ b2,
          float* __restrict__ Cf,
          __nv_bfloat16* __restrict__ Chi, __nv_bfloat16* __restrict__ Clo,
          int ldc, int relu)
{
    extern __shared__ char smem[];
    const uint32_t sbase = smem_to_u32(smem);
    const int tid = threadIdx.x;
    const int wid = tid >> 5;
    const int lid = tid & 31;
    const int m0  = blockIdx.y * 128;
    const int n0  = blockIdx.x * 128;
    const int wm  = (wid & 3) * 32;     // warp M offset in tile
    const int wn  = (wid >> 2) * 32;    // warp N offset in tile

    float acc[2][4][4];
    #pragma unroll
    for (int i = 0; i < 2; i++)
        #pragma unroll
        for (int j = 0; j < 4; j++)
            #pragma unroll
            for (int k = 0; k < 4; k++) acc[i][j][k] = 0.f;

    const int nch1 = K1 / 32;
    const int nch  = nch1 + K2 / 32;

    // per-thread load coords: one (row, 16B-group) per tile, 4 tiles
    const int lrow = tid >> 2;          // 0..127
    const int lcg  = tid & 3;           // 16B column group

    auto load_chunk = [&](int c) {
        const __nv_bfloat16 *pAh, *pAl, *pWh, *pWl;
        int kbase, Kc;
        if (c < nch1) { pAh = A1h; pAl = A1l; pWh = W1h; pWl = W1l; kbase = c * 32; Kc = K1; }
        else          { pAh = A2h; pAl = A2l; pWh = W2h; pWl = W2l; kbase = (c - nch1) * 32; Kc = K2; }
        const uint32_t st = sbase + (uint32_t)(c & (NSTAGE - 1)) * STAGEB;
        #pragma unroll
        for (int m = 0; m < 4; ++m) {
            const __nv_bfloat16* src = (m == 0) ? pAh : (m == 1) ? pAl : (m == 2) ? pWh : pWl;
            const int rb = (m < 2) ? m0 : n0;
            const void* g = src + (size_t)(rb + lrow) * Kc + kbase + lcg * 8;
            uint32_t s = st + m * TILEB + lrow * ROWB + lcg * 16;
            cp_async16(s, g);
        }
        cp_commit();
    };

    // prefetch 3 chunks (all our K sizes give nch >= 20)
    load_chunk(0);
    load_chunk(1);
    load_chunk(2);

    for (int c = 0; c < nch; ++c) {
        cp_wait<2>();          // chunk c resident
        __syncthreads();       // all threads' copies visible; stage (c+3)&3 free
        if (c + 3 < nch) load_chunk(c + 3);

        const uint32_t st = sbase + (uint32_t)(c & (NSTAGE - 1)) * STAGEB;
        #pragma unroll
        for (int ks = 0; ks < 2; ++ks) {
            const int kb = ks * 32;     // byte offset of 16-elem k-step
            uint32_t ah[2][4], al[2][4];
            #pragma unroll
            for (int mf = 0; mf < 2; ++mf) {
                uint32_t addr = st + (wm + mf * 16 + (lid & 15)) * ROWB
                              + kb + ((lid >> 4) * 16);
                ldsm_x4(ah[mf], addr);
                ldsm_x4(al[mf], addr + TILEB);
            }
            uint32_t bh[2][4], bl[2][4];
            #pragma unroll
            for (int ng = 0; ng < 2; ++ng) {
                int nrow = wn + ng * 16 + ((lid >> 4) << 3) + (lid & 7);
                int kof  = ((lid >> 3) & 1) * 16;
                uint32_t addr = st + 2 * TILEB + nrow * ROWB + kb + kof;
                ldsm_x4(bh[ng], addr);
                ldsm_x4(bl[ng], addr + TILEB);
            }
            #pragma unroll
            for (int mf = 0; mf < 2; ++mf)
                #pragma unroll
                for (int nf = 0; nf < 4; ++nf) {
                    const int ng = nf >> 1, hf = (nf & 1) * 2;
                    mma_bf16(acc[mf][nf], ah[mf], bh[ng][hf], bh[ng][hf + 1]);
                    mma_bf16(acc[mf][nf], ah[mf], bl[ng][hf], bl[ng][hf + 1]);
                    mma_bf16(acc[mf][nf], al[mf], bh[ng][hf], bh[ng][hf + 1]);
                }
        }
        __syncthreads();
    }

    // ---- epilogue ----
    const int g = lid >> 2;
    const int t = lid & 3;
    #pragma unroll
    for (int nf = 0; nf < 4; ++nf) {
        const int col = n0 + wn + nf * 8 + t * 2;
        float bb0 = b1[col],     bb1 = b1[col + 1];
        if (b2) { bb0 += b2[col]; bb1 += b2[col + 1]; }
        #pragma unroll
        for (int mf = 0; mf < 2; ++mf) {
            const int r0 = m0 + wm + mf * 16 + g;
            const int r1 = r0 + 8;
            float v00 = acc[mf][nf][0] + bb0;
            float v01 = acc[mf][nf][1] + bb1;
            float v10 = acc[mf][nf][2] + bb0;
            float v11 = acc[mf][nf][3] + bb1;
            if (relu) {
                v00 = fmaxf(v00, 0.f); v01 = fmaxf(v01, 0.f);
                v10 = fmaxf(v10, 0.f); v11 = fmaxf(v11, 0.f);
            }
            if (Chi) {
                __nv_bfloat16 h0b, l0b, h1b, l1b;
                __nv_bfloat162 th, tl;
                split1(v00, h0b, l0b); split1(v01, h1b, l1b);
                th.x = h0b; th.y = h1b; tl.x = l0b; tl.y = l1b;
                *reinterpret_cast<__nv_bfloat162*>(Chi + (size_t)r0 * ldc + col) = th;
                *reinterpret_cast<__nv_bfloat162*>(Clo + (size_t)r0 * ldc + col) = tl;
                split1(v10, h0b, l0b); split1(v11, h1b, l1b);
                th.x = h0b; th.y = h1b; tl.x = l0b; tl.y = l1b;
                *reinterpret_cast<__nv_bfloat162*>(Chi + (size_t)r1 * ldc + col) = th;
                *reinterpret_cast<__nv_bfloat162*>(Clo + (size_t)r1 * ldc + col) = tl;
            } else {
                *reinterpret_cast<float2*>(Cf + (size_t)r0 * ldc + col) = make_float2(v00, v01);
                *reinterpret_cast<float2*>(Cf + (size_t)r1 * ldc + col) = make_float2(v10, v11);
            }
        }
    }
}

// ================= launch =================
extern "C" void kernel_launch(void* const* d_in, const int* in_sizes, int n_in,
                              void* d_out, int out_size) {
    const int*   ids    = (const int*)  d_in[0];
    const float* h0     = (const float*)d_in[1];
    const float* c0     = (const float*)d_in[2];
    const float* enc    = (const float*)d_in[3];
    const float* emb    = (const float*)d_in[4];
    const float* w_ih   = (const float*)d_in[5];
    const float* w_hh   = (const float*)d_in[6];
    const float* b_ih   = (const float*)d_in[7];
    const float* b_hh   = (const float*)d_in[8];
    const float* w_enc  = (const float*)d_in[9];
    const float* b_enc  = (const float*)d_in[10];
    const float* w_pred = (const float*)d_in[11];
    const float* b_pred = (const float*)d_in[12];
    const float* w_out  = (const float*)d_in[13];
    const float* b_out  = (const float*)d_in[14];

    float* out    = (float*)d_out;
    float* logits = out;                                 // (B, V)
    float* h1f    = out + (size_t)B_ * V_;               // (L, B, H)
    float* c1f    = h1f + (size_t)L_ * B_ * H_;          // (L, B, H)

    float* gates;
    __nv_bfloat16 *xhi, *xlo, *h0hi, *h0lo, *h1hi, *h1lo, *enchi, *enclo, *zhi, *zlo;
    __nv_bfloat16 *wihhi, *wihlo, *whhhi, *whhlo, *wenchi, *wenclo,
                  *wpredhi, *wpredlo, *wouthi, *woutlo;
    cudaGetSymbolAddress((void**)&gates, g_gates);
    cudaGetSymbolAddress((void**)&xhi, g_xhi);       cudaGetSymbolAddress((void**)&xlo, g_xlo);
    cudaGetSymbolAddress((void**)&h0hi, g_h0hi);     cudaGetSymbolAddress((void**)&h0lo, g_h0lo);
    cudaGetSymbolAddress((void**)&h1hi, g_h1hi);     cudaGetSymbolAddress((void**)&h1lo, g_h1lo);
    cudaGetSymbolAddress((void**)&enchi, g_enchi);   cudaGetSymbolAddress((void**)&enclo, g_enclo);
    cudaGetSymbolAddress((void**)&zhi, g_zhi);       cudaGetSymbolAddress((void**)&zlo, g_zlo);
    cudaGetSymbolAddress((void**)&wihhi, g_wihhi);   cudaGetSymbolAddress((void**)&wihlo, g_wihlo);
    cudaGetSymbolAddress((void**)&whhhi, g_whhhi);   cudaGetSymbolAddress((void**)&whhlo, g_whhlo);
    cudaGetSymbolAddress((void**)&wenchi, g_wenchi); cudaGetSymbolAddress((void**)&wenclo, g_wenclo);
    cudaGetSymbolAddress((void**)&wpredhi, g_wpredhi); cudaGetSymbolAddress((void**)&wpredlo, g_wpredlo);
    cudaGetSymbolAddress((void**)&wouthi, g_wouthi); cudaGetSymbolAddress((void**)&woutlo, g_woutlo);

    cudaFuncSetAttribute(gemm_hmma, cudaFuncAttributeMaxDynamicSharedMemorySize, SMEMB);

    const int T = 256;
    auto grid1d = [](long n) { return (int)((n + 255) / 256); };

    // ---- splits ----
    gather_split<<<grid1d(B_ * (E_ / 4)), T>>>(ids, (const float4*)emb,
                                               (__nv_bfloat162*)xhi, (__nv_bfloat162*)xlo);
    split_bf16<<<grid1d((long)L_ * B_ * H_ / 4), T>>>((const float4*)h0,
        (__nv_bfloat162*)h0hi, (__nv_bfloat162*)h0lo, L_ * B_ * H_ / 4);
    split_bf16<<<grid1d((long)B_ * D_ / 4), T>>>((const float4*)enc,
        (__nv_bfloat162*)enchi, (__nv_bfloat162*)enclo, B_ * D_ / 4);
    split_bf16<<<grid1d((long)L_ * 4 * H_ * H_ / 4), T>>>((const float4*)w_ih,
        (__nv_bfloat162*)wihhi, (__nv_bfloat162*)wihlo, L_ * 4 * H_ * H_ / 4);
    split_bf16<<<grid1d((long)L_ * 4 * H_ * H_ / 4), T>>>((const float4*)w_hh,
        (__nv_bfloat162*)whhhi, (__nv_bfloat162*)whhlo, L_ * 4 * H_ * H_ / 4);
    split_bf16<<<grid1d((long)J_ * D_ / 4), T>>>((const float4*)w_enc,
        (__nv_bfloat162*)wenchi, (__nv_bfloat162*)wenclo, J_ * D_ / 4);
    split_bf16<<<grid1d((long)J_ * H_ / 4), T>>>((const float4*)w_pred,
        (__nv_bfloat162*)wpredhi, (__nv_bfloat162*)wpredlo, J_ * H_ / 4);
    split_bf16<<<grid1d((long)V_ * J_ / 4), T>>>((const float4*)w_out,
        (__nv_bfloat162*)wouthi, (__nv_bfloat162*)woutlo, V_ * J_ / 4);

    const int WIH = 4 * H_ * H_;     // per-layer w_ih/w_hh elems
    const int BH  = B_ * H_;         // per-layer h slice elems

    dim3 blk(512);
    dim3 grdG(4 * H_ / 128, B_ / 128);   // 20 x 64

    // ---- layer 0 gates ----
    gemm_hmma<<<grdG, blk, SMEMB>>>(
        xhi, xlo, wihhi, wihlo, H_,
        h0hi, h0lo, whhhi, whhlo, H_,
        b_ih, b_hh, gates, nullptr, nullptr, 4 * H_, 0);
    lstm_cell<<<grid1d((long)BH), T>>>(gates, c0, h1f, c1f, h1hi, h1lo);

    // ---- layer 1 gates ----
    gemm_hmma<<<grdG, blk, SMEMB>>>(
        h1hi, h1lo, wihhi + WIH, wihlo + WIH, H_,
        h0hi + BH, h0lo + BH, whhhi + WIH, whhlo + WIH, H_,
        b_ih + 4 * H_, b_hh + 4 * H_, gates, nullptr, nullptr, 4 * H_, 0);
    lstm_cell<<<grid1d((long)BH), T>>>(gates, c0 + BH, h1f + BH, c1f + BH,
                                       h1hi + BH, h1lo + BH);

    // ---- joint: relu(enc*w_enc^T + pred*w_pred^T + b) -> split z ----
    dim3 grdJ(J_ / 128, B_ / 128);       // 5 x 64
    gemm_hmma<<<grdJ, blk, SMEMB>>>(
        enchi, enclo, wenchi, wenclo, D_,
        h1hi + BH, h1lo + BH, wpredhi, wpredlo, H_,
        b_enc, b_pred, nullptr, zhi, zlo, J_, 1);

    // ---- logits = z*w_out^T + b_out ----
    dim3 grdO(V_ / 128, B_ / 128);       // 8 x 64
    gemm_hmma<<<grdO, blk, SMEMB>>>(
        zhi, zlo, wouthi, woutlo, J_,
        nullptr, nullptr, nullptr, nullptr, 0,
        b_out, nullptr, logits, nullptr, nullptr, V_, 0);
}

// round 5
// speedup vs baseline: 1.5999x; 1.5999x over previous
#include <cuda_runtime.h>
#include <cuda_fp16.h>
#include <cstdint>

// ---------------- problem dims ----------------
#define B_ 8192
#define V_ 1024
#define E_ 640
#define H_ 640
#define L_ 2
#define D_ 512
#define J_ 640

// ---------------- GEMM smem layout ----------------
#define ROWB   80                    // bytes per smem row: 32 fp16 (64B) + 16B pad
#define TILEB  (128 * ROWB)          // one 128x32 fp16 tile = 10240 B
#define NSTAGE 4

// ================= low-level helpers (base sm_100 ISA only) =================
__device__ __forceinline__ uint32_t smem_to_u32(const void* p) {
    uint32_t a;
    asm("{ .reg .u64 t; cvta.to.shared.u64 t, %1; cvt.u32.u64 %0, t; }"
        : "=r"(a) : "l"(p));
    return a;
}
__device__ __forceinline__ void cp_async16(uint32_t saddr, const void* gptr) {
    asm volatile("cp.async.cg.shared.global [%0], [%1], 16;"
                 :: "r"(saddr), "l"(gptr));
}
__device__ __forceinline__ void cp_commit() {
    asm volatile("cp.async.commit_group;");
}
template <int N>
__device__ __forceinline__ void cp_wait() {
    asm volatile("cp.async.wait_group %0;" :: "n"(N));
}
__device__ __forceinline__ void ldsm_x4(uint32_t* r, uint32_t addr) {
    asm volatile("ldmatrix.sync.aligned.m8n8.x4.shared.b16 {%0,%1,%2,%3}, [%4];"
                 : "=r"(r[0]), "=r"(r[1]), "=r"(r[2]), "=r"(r[3]) : "r"(addr));
}
__device__ __forceinline__ void mma_fp16(float* c, const uint32_t* a,
                                         uint32_t b0, uint32_t b1) {
    asm volatile(
        "mma.sync.aligned.m16n8k16.row.col.f32.f16.f16.f32 "
        "{%0,%1,%2,%3}, {%4,%5,%6,%7}, {%8,%9}, {%0,%1,%2,%3};"
        : "+f"(c[0]), "+f"(c[1]), "+f"(c[2]), "+f"(c[3])
        : "r"(a[0]), "r"(a[1]), "r"(a[2]), "r"(a[3]), "r"(b0), "r"(b1));
}

// ================= scratch (no allocations allowed) =================
__device__ float g_gates[B_ * 4 * H_];
// single-precision-pass fp16 operands (gate GEMMs)
__device__ __align__(16) __half g_xh[B_ * E_];
__device__ __align__(16) __half g_h0h[L_ * B_ * H_];
__device__ __align__(16) __half g_h1s[B_ * H_];                 // layer-0 h1 (single)
__device__ __align__(16) __half g_wih[L_ * 4 * H_ * H_];
__device__ __align__(16) __half g_whh[L_ * 4 * H_ * H_];
// split fp16 operands (joint + output GEMMs)
__device__ __align__(16) __half g_predhi[B_ * H_], g_predlo[B_ * H_];
__device__ __align__(16) __half g_enchi[B_ * D_],  g_enclo[B_ * D_];
__device__ __align__(16) __half g_zhi[B_ * J_],    g_zlo[B_ * J_];
__device__ __align__(16) __half g_wenchi[J_ * D_], g_wenclo[J_ * D_];
__device__ __align__(16) __half g_wpredhi[J_ * H_], g_wpredlo[J_ * H_];
__device__ __align__(16) __half g_wouthi[V_ * J_],  g_woutlo[V_ * J_];

// ================= elementwise kernels =================
__device__ __forceinline__ void split1h(float v, __half& h, __half& l) {
    h = __float2half_rn(v);
    l = __float2half_rn(v - __half2float(h));
}

// fp32 -> fp16 (single)
__global__ void conv_h(const float4* __restrict__ in, __half2* __restrict__ out, int n4) {
    int i = blockIdx.x * blockDim.x + threadIdx.x;
    if (i >= n4) return;
    float4 v = in[i];
    out[2 * i]     = __floats2half2_rn(v.x, v.y);
    out[2 * i + 1] = __floats2half2_rn(v.z, v.w);
}

// fp32 -> (hi, lo) fp16 split
__global__ void conv_h_split(const float4* __restrict__ in,
                             __half2* __restrict__ hi,
                             __half2* __restrict__ lo, int n4) {
    int i = blockIdx.x * blockDim.x + threadIdx.x;
    if (i >= n4) return;
    float4 v = in[i];
    __half hx, lx, hy, ly, hz, lz, hw, lw;
    split1h(v.x, hx, lx); split1h(v.y, hy, ly);
    split1h(v.z, hz, lz); split1h(v.w, hw, lw);
    hi[2 * i]     = __halves2half2(hx, hy);
    hi[2 * i + 1] = __halves2half2(hz, hw);
    lo[2 * i]     = __halves2half2(lx, ly);
    lo[2 * i + 1] = __halves2half2(lz, lw);
}

// embedding gather -> fp16 single
__global__ void gather_h(const int* __restrict__ ids,
                         const float4* __restrict__ emb,
                         __half2* __restrict__ x) {
    int i = blockIdx.x * blockDim.x + threadIdx.x;   // over B_*(E_/4)
    if (i >= B_ * (E_ / 4)) return;
    int b = i / (E_ / 4);
    int q = i - b * (E_ / 4);
    float4 v = emb[(size_t)ids[b] * (E_ / 4) + q];
    x[2 * i]     = __floats2half2_rn(v.x, v.y);
    x[2 * i + 1] = __floats2half2_rn(v.z, v.w);
}

__device__ __forceinline__ float sigmoidf_(float x) {
    return 1.0f / (1.0f + expf(-x));
}

// LSTM cell. If h1hi != nullptr -> write hi/lo fp16 split; else write single fp16 to h1s.
__global__ void lstm_cell(const float* __restrict__ gates,
                          const float* __restrict__ c0,
                          float* __restrict__ h1f, float* __restrict__ c1f,
                          __half* __restrict__ h1s,
                          __half* __restrict__ h1hi, __half* __restrict__ h1lo) {
    int i = blockIdx.x * blockDim.x + threadIdx.x;   // over B_*H_
    if (i >= B_ * H_) return;
    int b = i / H_;
    int n = i - b * H_;
    const float* g = gates + (size_t)b * (4 * H_);
    float ig = sigmoidf_(g[n]);
    float fg = sigmoidf_(g[H_ + n]);
    float gg = tanhf(g[2 * H_ + n]);
    float og = sigmoidf_(g[3 * H_ + n]);
    float c  = fg * c0[i] + ig * gg;
    float h  = og * tanhf(c);
    c1f[i] = c;
    h1f[i] = h;
    if (h1hi) {
        __half hh, hl;
        split1h(h, hh, hl);
        h1hi[i] = hh;
        h1lo[i] = hl;
    } else {
        h1s[i] = __float2half_rn(h);
    }
}

// ================= fp16 HMMA GEMM (templated on split mode) =================
// SPLIT=0: C = A1*W1^T (+ A2*W2^T) single-pass fp16 (1 MMA per pair)
// SPLIT=1: 2-way fp16 split, hi*hi + hi*lo + lo*hi (3 MMAs per pair)
// CTA tile 128x128, 512 threads = 16 warps (4x4), warp tile 32x32,
// K chunks of 32, 4-stage cp.async pipeline.
// If Chi != nullptr: write hi/lo fp16 split of C; else fp32 to Cf.
template <int SPLIT>
__global__ void __launch_bounds__(512, 1)
gemm_hmma(const __half* __restrict__ A1h, const __half* __restrict__ A1l,
          const __half* __restrict__ W1h, const __half* __restrict__ W1l, int K1,
          const __half* __restrict__ A2h, const __half* __restrict__ A2l,
          const __half* __restrict__ W2h, const __half* __restrict__ W2l, int K2,
          const float* __restrict__ b1, const float* __restrict__ b2,
          float* __restrict__ Cf,
          __half* __restrict__ Chi, __half* __restrict__ Clo,
          int ldc, int relu)
{
    constexpr int TILES  = SPLIT ? 4 : 2;
    constexpr int WOFF   = SPLIT ? 2 : 1;         // tile index of W_hi in stage
    constexpr int STAGEB = TILES * TILEB;

    extern __shared__ char smem[];
    const uint32_t sbase = smem_to_u32(smem);
    const int tid = threadIdx.x;
    const int wid = tid >> 5;
    const int lid = tid & 31;
    const int m0  = blockIdx.y * 128;
    const int n0  = blockIdx.x * 128;
    const int wm  = (wid & 3) * 32;     // warp M offset in tile
    const int wn  = (wid >> 2) * 32;    // warp N offset in tile

    float acc[2][4][4];
    #pragma unroll
    for (int i = 0; i < 2; i++)
        #pragma unroll
        for (int j = 0; j < 4; j++)
            #pragma unroll
            for (int k = 0; k < 4; k++) acc[i][j][k] = 0.f;

    const int nch1 = K1 / 32;
    const int nch  = nch1 + K2 / 32;

    // per-thread load coords: one (row, 16B-group) per tile
    const int lrow = tid >> 2;          // 0..127
    const int lcg  = tid & 3;           // 16B column group

    auto load_chunk = [&](int c) {
        const __half* srcs[4];
        int kbase, Kc;
        if (c < nch1) {
            kbase = c * 32; Kc = K1;
            if (SPLIT) { srcs[0] = A1h; srcs[1] = A1l; srcs[2] = W1h; srcs[3] = W1l; }
            else       { srcs[0] = A1h; srcs[1] = W1h; }
        } else {
            kbase = (c - nch1) * 32; Kc = K2;
            if (SPLIT) { srcs[0] = A2h; srcs[1] = A2l; srcs[2] = W2h; srcs[3] = W2l; }
            else       { srcs[0] = A2h; srcs[1] = W2h; }
        }
        const uint32_t st = sbase + (uint32_t)(c & (NSTAGE - 1)) * STAGEB;
        #pragma unroll
        for (int m = 0; m < TILES; ++m) {
            const int rb = (m < WOFF) ? m0 : n0;
            const void* g = srcs[m] + (size_t)(rb + lrow) * Kc + kbase + lcg * 8;
            uint32_t s = st + m * TILEB + lrow * ROWB + lcg * 16;
            cp_async16(s, g);
        }
        cp_commit();
    };

    // prefetch 3 chunks (all K sizes give nch >= 16)
    load_chunk(0);
    load_chunk(1);
    load_chunk(2);

    for (int c = 0; c < nch; ++c) {
        cp_wait<2>();          // chunk c resident
        __syncthreads();       // stage (c+3)&3 free for reuse
        if (c + 3 < nch) load_chunk(c + 3);

        const uint32_t st = sbase + (uint32_t)(c & (NSTAGE - 1)) * STAGEB;
        #pragma unroll
        for (int ks = 0; ks < 2; ++ks) {
            const int kb = ks * 32;     // byte offset of 16-elem k-step
            uint32_t ah[2][4], al[2][4];
            #pragma unroll
            for (int mf = 0; mf < 2; ++mf) {
                uint32_t addr = st + (wm + mf * 16 + (lid & 15)) * ROWB
                              + kb + ((lid >> 4) * 16);
                ldsm_x4(ah[mf], addr);
                if (SPLIT) ldsm_x4(al[mf], addr + TILEB);
            }
            uint32_t bh[2][4], bl[2][4];
            #pragma unroll
            for (int ng = 0; ng < 2; ++ng) {
                int nrow = wn + ng * 16 + ((lid >> 4) << 3) + (lid & 7);
                int kof  = ((lid >> 3) & 1) * 16;
                uint32_t addr = st + WOFF * TILEB + nrow * ROWB + kb + kof;
                ldsm_x4(bh[ng], addr);
                if (SPLIT) ldsm_x4(bl[ng], addr + TILEB);
            }
            #pragma unroll
            for (int mf = 0; mf < 2; ++mf)
                #pragma unroll
                for (int nf = 0; nf < 4; ++nf) {
                    const int ng = nf >> 1, hf = (nf & 1) * 2;
                    mma_fp16(acc[mf][nf], ah[mf], bh[ng][hf], bh[ng][hf + 1]);
                    if (SPLIT) {
                        mma_fp16(acc[mf][nf], ah[mf], bl[ng][hf], bl[ng][hf + 1]);
                        mma_fp16(acc[mf][nf], al[mf], bh[ng][hf], bh[ng][hf + 1]);
                    }
                }
        }
        __syncthreads();
    }

    // ---- epilogue ----
    const int g = lid >> 2;
    const int t = lid & 3;
    #pragma unroll
    for (int nf = 0; nf < 4; ++nf) {
        const int col = n0 + wn + nf * 8 + t * 2;
        float bb0 = b1[col],     bb1 = b1[col + 1];
        if (b2) { bb0 += b2[col]; bb1 += b2[col + 1]; }
        #pragma unroll
        for (int mf = 0; mf < 2; ++mf) {
            const int r0 = m0 + wm + mf * 16 + g;
            const int r1 = r0 + 8;
            float v00 = acc[mf][nf][0] + bb0;
            float v01 = acc[mf][nf][1] + bb1;
            float v10 = acc[mf][nf][2] + bb0;
            float v11 = acc[mf][nf][3] + bb1;
            if (relu) {
                v00 = fmaxf(v00, 0.f); v01 = fmaxf(v01, 0.f);
                v10 = fmaxf(v10, 0.f); v11 = fmaxf(v11, 0.f);
            }
            if (Chi) {
                __half h0b, l0b, h1b, l1b;
                split1h(v00, h0b, l0b); split1h(v01, h1b, l1b);
                *reinterpret_cast<__half2*>(Chi + (size_t)r0 * ldc + col) = __halves2half2(h0b, h1b);
                *reinterpret_cast<__half2*>(Clo + (size_t)r0 * ldc + col) = __halves2half2(l0b, l1b);
                split1h(v10, h0b, l0b); split1h(v11, h1b, l1b);
                *reinterpret_cast<__half2*>(Chi + (size_t)r1 * ldc + col) = __halves2half2(h0b, h1b);
                *reinterpret_cast<__half2*>(Clo + (size_t)r1 * ldc + col) = __halves2half2(l0b, l1b);
            } else {
                *reinterpret_cast<float2*>(Cf + (size_t)r0 * ldc + col) = make_float2(v00, v01);
                *reinterpret_cast<float2*>(Cf + (size_t)r1 * ldc + col) = make_float2(v10, v11);
            }
        }
    }
}

// ================= launch =================
extern "C" void kernel_launch(void* const* d_in, const int* in_sizes, int n_in,
                              void* d_out, int out_size) {
    const int*   ids    = (const int*)  d_in[0];
    const float* h0     = (const float*)d_in[1];
    const float* c0     = (const float*)d_in[2];
    const float* enc    = (const float*)d_in[3];
    const float* emb    = (const float*)d_in[4];
    const float* w_ih   = (const float*)d_in[5];
    const float* w_hh   = (const float*)d_in[6];
    const float* b_ih   = (const float*)d_in[7];
    const float* b_hh   = (const float*)d_in[8];
    const float* w_enc  = (const float*)d_in[9];
    const float* b_enc  = (const float*)d_in[10];
    const float* w_pred = (const float*)d_in[11];
    const float* b_pred = (const float*)d_in[12];
    const float* w_out  = (const float*)d_in[13];
    const float* b_out  = (const float*)d_in[14];

    float* out    = (float*)d_out;
    float* logits = out;                                 // (B, V)
    float* h1f    = out + (size_t)B_ * V_;               // (L, B, H)
    float* c1f    = h1f + (size_t)L_ * B_ * H_;          // (L, B, H)

    float* gates;
    __half *xh, *h0h, *h1s, *wih, *whh;
    __half *predhi, *predlo, *enchi, *enclo, *zhi, *zlo;
    __half *wenchi, *wenclo, *wpredhi, *wpredlo, *wouthi, *woutlo;
    cudaGetSymbolAddress((void**)&gates, g_gates);
    cudaGetSymbolAddress((void**)&xh,  g_xh);
    cudaGetSymbolAddress((void**)&h0h, g_h0h);
    cudaGetSymbolAddress((void**)&h1s, g_h1s);
    cudaGetSymbolAddress((void**)&wih, g_wih);
    cudaGetSymbolAddress((void**)&whh, g_whh);
    cudaGetSymbolAddress((void**)&predhi, g_predhi); cudaGetSymbolAddress((void**)&predlo, g_predlo);
    cudaGetSymbolAddress((void**)&enchi, g_enchi);   cudaGetSymbolAddress((void**)&enclo, g_enclo);
    cudaGetSymbolAddress((void**)&zhi, g_zhi);       cudaGetSymbolAddress((void**)&zlo, g_zlo);
    cudaGetSymbolAddress((void**)&wenchi, g_wenchi); cudaGetSymbolAddress((void**)&wenclo, g_wenclo);
    cudaGetSymbolAddress((void**)&wpredhi, g_wpredhi); cudaGetSymbolAddress((void**)&wpredlo, g_wpredlo);
    cudaGetSymbolAddress((void**)&wouthi, g_wouthi); cudaGetSymbolAddress((void**)&woutlo, g_woutlo);

    const int SMEM0 = NSTAGE * 2 * TILEB;   // 81920
    const int SMEM1 = NSTAGE * 4 * TILEB;   // 163840
    cudaFuncSetAttribute(gemm_hmma<0>, cudaFuncAttributeMaxDynamicSharedMemorySize, SMEM0);
    cudaFuncSetAttribute(gemm_hmma<1>, cudaFuncAttributeMaxDynamicSharedMemorySize, SMEM1);

    const int T = 256;
    auto grid1d = [](long n) { return (int)((n + 255) / 256); };

    // ---- conversions ----
    gather_h<<<grid1d(B_ * (E_ / 4)), T>>>(ids, (const float4*)emb, (__half2*)xh);
    conv_h<<<grid1d((long)L_ * B_ * H_ / 4), T>>>((const float4*)h0, (__half2*)h0h,
                                                  L_ * B_ * H_ / 4);
    conv_h<<<grid1d((long)L_ * 4 * H_ * H_ / 4), T>>>((const float4*)w_ih, (__half2*)wih,
                                                      L_ * 4 * H_ * H_ / 4);
    conv_h<<<grid1d((long)L_ * 4 * H_ * H_ / 4), T>>>((const float4*)w_hh, (__half2*)whh,
                                                      L_ * 4 * H_ * H_ / 4);
    conv_h_split<<<grid1d((long)B_ * D_ / 4), T>>>((const float4*)enc,
        (__half2*)enchi, (__half2*)enclo, B_ * D_ / 4);
    conv_h_split<<<grid1d((long)J_ * D_ / 4), T>>>((const float4*)w_enc,
        (__half2*)wenchi, (__half2*)wenclo, J_ * D_ / 4);
    conv_h_split<<<grid1d((long)J_ * H_ / 4), T>>>((const float4*)w_pred,
        (__half2*)wpredhi, (__half2*)wpredlo, J_ * H_ / 4);
    conv_h_split<<<grid1d((long)V_ * J_ / 4), T>>>((const float4*)w_out,
        (__half2*)wouthi, (__half2*)woutlo, V_ * J_ / 4);

    const int WIH = 4 * H_ * H_;     // per-layer w_ih/w_hh elems
    const int BH  = B_ * H_;         // per-layer h slice elems

    dim3 blk(512);
    dim3 grdG(4 * H_ / 128, B_ / 128);   // 20 x 64

    // ---- layer 0 gates: x*w_ih0^T + h0[0]*w_hh0^T (single-pass fp16) ----
    gemm_hmma<0><<<grdG, blk, SMEM0>>>(
        xh, nullptr, wih, nullptr, H_,
        h0h, nullptr, whh, nullptr, H_,
        b_ih, b_hh, gates, nullptr, nullptr, 4 * H_, 0);
    lstm_cell<<<grid1d((long)BH), T>>>(gates, c0, h1f, c1f, h1s, nullptr, nullptr);

    // ---- layer 1 gates ----
    gemm_hmma<0><<<grdG, blk, SMEM0>>>(
        h1s, nullptr, wih + WIH, nullptr, H_,
        h0h + BH, nullptr, whh + WIH, nullptr, H_,
        b_ih + 4 * H_, b_hh + 4 * H_, gates, nullptr, nullptr, 4 * H_, 0);
    lstm_cell<<<grid1d((long)BH), T>>>(gates, c0 + BH, h1f + BH, c1f + BH,
                                       nullptr, predhi, predlo);

    // ---- joint: relu(enc*w_enc^T + pred*w_pred^T + b) -> z hi/lo (split GEMM) ----
    dim3 grdJ(J_ / 128, B_ / 128);       // 5 x 64
    gemm_hmma<1><<<grdJ, blk, SMEM1>>>(
        enchi, enclo, wenchi, wenclo, D_,
        predhi, predlo, wpredhi, wpredlo, H_,
        b_enc, b_pred, nullptr, zhi, zlo, J_, 1);

    // ---- logits = z*w_out^T + b_out (split GEMM) ----
    dim3 grdO(V_ / 128, B_ / 128);       // 8 x 64
    gemm_hmma<1><<<grdO, blk, SMEM1>>>(
        zhi, zlo, wouthi, woutlo, J_,
        nullptr, nullptr, nullptr, nullptr, 0,
        b_out, nullptr, logits, nullptr, nullptr, V_, 0);
}